// round 4
// baseline (speedup 1.0000x reference)
#include <cuda_runtime.h>
#include <cuda_bf16.h>
#include <utility>

// SpeDCT: out[b,:,h,w] = Dinv @ diag(weight[h,w,:]) @ D @ x[b,:,h,w]
// C = 28 channels, H = W = 256, B = 16.
//
// All 2*28*28 DCT coefficients are compile-time float immediates (constexpr
// cos via Taylor in double, template-indexed so ptxas emits FFMA-imm which
// runs at rt_SMSP=1 on sm_103a — 2x the 3-register FFMA rate).
// DCT symmetry (D[k][27-n] = (-1)^k D[k][n]) halves the FMA count:
// ~784 FMA/pixel instead of 1568.

static constexpr int  Cc  = 28;
static constexpr int  HWp = 256 * 256;

// cos(pi * m / 56), exact-to-double via range reduction + Taylor.
// __host__ __device__ so it is legal in device constexpr contexts without
// --expt-relaxed-constexpr (evaluation still happens at compile time).
__host__ __device__ constexpr double cospi56(int m) {
    int mm = m % 112;            // cos period in m is 112
    if (mm < 0) mm += 112;
    if (mm > 56) mm = 112 - mm;  // cos(2pi - x) = cos(x); now angle in [0, pi]
    double x  = 3.141592653589793238462643383279502884 * (double)mm / 56.0;
    double x2 = x * x, t = 1.0, s = 1.0;
    for (int i = 1; i <= 24; ++i) { t *= -x2 / (double)((2 * i - 1) * (2 * i)); s += t; }
    return s;
}

// Forward DCT-II matrix entry: D[k][n] = 2*cos(pi*(2n+1)k/56)
template <int k, int n>
__device__ __forceinline__ float cD() {
    constexpr float v = (float)(2.0 * cospi56((2 * n + 1) * k));
    return v;
}
// Inverse matrix entry: Dinv[n][k] = cos(pi*(2n+1)k/56) * (k==0 ? 0.5 : 1.0) / 28
template <int n, int k>
__device__ __forceinline__ float cDI() {
    constexpr float v = (float)(cospi56((2 * n + 1) * k) * ((k == 0) ? 0.5 : 1.0) / 28.0);
    return v;
}

// Stage 1 inner: for pair index n, accumulate all 28 spectral bins.
// Even k uses (x_n + x_{27-n}), odd k uses (x_n - x_{27-n}).
template <int n, int... ks>
__device__ __forceinline__ void s1_acc(float (&xd)[Cc], float s, float d,
                                       std::integer_sequence<int, ks...>) {
    ((xd[ks] = fmaf(((ks & 1) ? d : s), cD<ks, n>(), xd[ks])), ...);
}

template <int... ns>
__device__ __forceinline__ void stage1(float (&xd)[Cc], const float* __restrict__ xp,
                                       std::integer_sequence<int, ns...>) {
    (([&] {
         float xa = xp[(size_t)ns * HWp];
         float xb = xp[(size_t)(27 - ns) * HWp];
         s1_acc<ns>(xd, xa + xb, xa - xb, std::make_integer_sequence<int, Cc>{});
     }()),
     ...);
}

// Stage 2: even-k and odd-k partial dots; out[n] = E + O, out[27-n] = E - O.
template <int n, int... js>
__device__ __forceinline__ float dotE(const float (&xd)[Cc],
                                      std::integer_sequence<int, js...>) {
    float e = 0.f;
    ((e = fmaf(xd[2 * js], cDI<n, 2 * js>(), e)), ...);
    return e;
}
template <int n, int... js>
__device__ __forceinline__ float dotO(const float (&xd)[Cc],
                                      std::integer_sequence<int, js...>) {
    float o = 0.f;
    ((o = fmaf(xd[2 * js + 1], cDI<n, 2 * js + 1>(), o)), ...);
    return o;
}

template <int... ns>
__device__ __forceinline__ void stage2(const float (&xd)[Cc], float* __restrict__ op,
                                       std::integer_sequence<int, ns...>) {
    (([&] {
         float E = dotE<ns>(xd, std::make_integer_sequence<int, 14>{});
         float O = dotO<ns>(xd, std::make_integer_sequence<int, 14>{});
         op[(size_t)ns * HWp]        = E + O;
         op[(size_t)(27 - ns) * HWp] = E - O;
     }()),
     ...);
}

__global__ void __launch_bounds__(256)
spedct_kernel(const float* __restrict__ x, const float* __restrict__ w,
              float* __restrict__ out) {
    const int hw = blockIdx.y * blockDim.x + threadIdx.x;  // 0..65535
    const int b  = blockIdx.x;                             // 0..15 (fastest -> weight L2 reuse)

    const float* xp = x + (size_t)b * Cc * HWp + hw;
    float*       op = out + (size_t)b * Cc * HWp + hw;

    float xd[Cc];
#pragma unroll
    for (int k = 0; k < Cc; ++k) xd[k] = 0.f;

    // Forward DCT along channels (folded, 392 FMA)
    stage1(xd, xp, std::make_integer_sequence<int, 14>{});

    // Per-pixel spectral filter. weight[h,w,:] is 28 contiguous floats;
    // hw*28*4 = hw*112 bytes is 16B-aligned, so float4 loads are legal.
    const float4* wv = reinterpret_cast<const float4*>(w + (size_t)hw * Cc);
#pragma unroll
    for (int j = 0; j < 7; ++j) {
        float4 w4 = wv[j];
        xd[4 * j + 0] *= w4.x;
        xd[4 * j + 1] *= w4.y;
        xd[4 * j + 2] *= w4.z;
        xd[4 * j + 3] *= w4.w;
    }

    // Inverse DCT along channels (folded, 392 FMA) + store
    stage2(xd, op, std::make_integer_sequence<int, 14>{});
}

extern "C" void kernel_launch(void* const* d_in, const int* in_sizes, int n_in,
                              void* d_out, int out_size) {
    const float* x = (const float*)d_in[0];   // [16, 28, 256, 256] f32
    const float* w = (const float*)d_in[1];   // [256, 256, 28] f32
    float*     out = (float*)d_out;           // [16, 28, 256, 256] f32

    dim3 grid(16, HWp / 256);  // batch fastest: 16 adjacent blocks share weight slice in L2
    spedct_kernel<<<grid, 256>>>(x, w, out);
}